// round 7
// baseline (speedup 1.0000x reference)
#include <cuda_runtime.h>

#define NN 100000
#define EMAX 2000000
#define EPSV 1.4142135623730951f
#define ONE_PE 2.4142135623730951f          /* 1 + sqrt(2) */
#define INV_SQRT128 0.08838834764831845f    /* 1/sqrt(128) */

// ---------------- scratch (device globals: allocation-free) ----------------
__device__ int   g_is32;
__device__ float g_inv[NN];
__device__ int   g_cnt_t[NN];
__device__ int   g_cnt_s[NN];
__device__ int   g_fill[NN];
__device__ int   g_rowptr[NN + 1];
__device__ int   g_perm[EMAX];
__device__ float g_bufA[(size_t)NN * 128];
__device__ float g_bufB[(size_t)NN * 128];
__device__ float g_bufC[(size_t)NN * 128];
__device__ float g_z1[(size_t)NN * 512];
__device__ float g_z2[(size_t)NN * 512];

// device-side scratch-buffer resolver (no host cudaGetSymbolAddress needed)
__device__ __forceinline__ float* dbuf(int id) {
    switch (id) {
        case 0: return g_bufA;
        case 1: return g_bufB;
        case 2: return g_bufC;
        case 3: return g_z1;
        case 4: return g_z2;
        default: return nullptr;
    }
}

// ---------------- packed fp32x2 helpers (Blackwell FFMA2 path) -------------
__device__ __forceinline__ unsigned long long pack2(float x, float y) {
    unsigned long long r;
    asm("mov.b64 %0, {%1, %2};" : "=l"(r) : "f"(x), "f"(y));
    return r;
}
__device__ __forceinline__ void ffma2(unsigned long long &d,
                                      unsigned long long a,
                                      unsigned long long b) {
    asm("fma.rn.f32x2 %0, %1, %2, %0;" : "+l"(d) : "l"(a), "l"(b));
}
__device__ __forceinline__ float2 unpack2(unsigned long long v) {
    float x, y;
    asm("mov.b64 {%0, %1}, %2;" : "=f"(x), "=f"(y) : "l"(v));
    return make_float2(x, y);
}

// ---------------- edge dtype detection -------------------------------------
// JAX without x64 silently downgrades int64 edge_index to int32. Detect by
// scanning 8-byte words: genuine int64 node ids (< NN) have zero high words;
// int32 pairs almost surely produce a word > 0xFFFFFFFF.
__global__ void detect_kernel(const void* __restrict__ ei) {
    const unsigned long long* p = (const unsigned long long*)ei;
    int is32 = 0;
    for (int i = 0; i < 2048; i++)
        if (p[i] > 0xFFFFFFFFull) { is32 = 1; break; }
    g_is32 = is32;
}

__device__ __forceinline__ void load_edge(const void* ei, int E, int e,
                                          int is32, int& t, int& s) {
    if (is32) {
        const int* p = (const int*)ei;
        t = p[e]; s = p[E + e];
    } else {
        const long long* p = (const long long*)ei;
        t = (int)p[e]; s = (int)p[E + e];
    }
}

// ---------------- graph preprocessing --------------------------------------
__global__ void zero_kernel() {
    int i = blockIdx.x * blockDim.x + threadIdx.x;
    if (i < NN) { g_cnt_t[i] = 0; g_cnt_s[i] = 0; g_fill[i] = 0; }
}

__global__ void hist_kernel(const void* __restrict__ ei, int E) {
    int e = blockIdx.x * blockDim.x + threadIdx.x;
    if (e >= E) return;
    int t, s;
    load_edge(ei, E, e, g_is32, t, s);
    if ((unsigned)t < NN) atomicAdd(&g_cnt_t[t], 1);
    if ((unsigned)s < NN) atomicAdd(&g_cnt_s[s], 1);
}

// single-block exclusive scan of cnt_t -> rowptr, plus inv-norm from cnt_s
__global__ void scan_kernel(int E) {
    __shared__ int sh[1024];
    const int CH = (NN + 1023) / 1024;   // 98
    int t = threadIdx.x;
    int lo = t * CH;
    int hi = min(lo + CH, NN);
    int s = 0;
    for (int k = lo; k < hi; k++) s += g_cnt_t[k];
    sh[t] = s;
    __syncthreads();
    // Hillis-Steele inclusive scan
    for (int off = 1; off < 1024; off <<= 1) {
        int v = sh[t];
        int u = (t >= off) ? sh[t - off] : 0;
        __syncthreads();
        sh[t] = v + u;
        __syncthreads();
    }
    int run = (t == 0) ? 0 : sh[t - 1];
    for (int k = lo; k < hi; k++) {
        g_rowptr[k] = run;
        run += g_cnt_t[k];
        g_inv[k] = INV_SQRT128 / (1.0f + EPSV + (float)g_cnt_s[k]);
    }
    if (t == 0) g_rowptr[NN] = E;
}

__global__ void fill_kernel(const void* __restrict__ ei, int E) {
    int e = blockIdx.x * blockDim.x + threadIdx.x;
    if (e >= E) return;
    int t, s;
    load_edge(ei, E, e, g_is32, t, s);
    if ((unsigned)t < NN && (unsigned)s < NN) {
        int p = atomicAdd(&g_fill[t], 1);
        int pos = g_rowptr[t] + p;
        if ((unsigned)pos < EMAX) g_perm[pos] = s;
    }
}

// ---------------- GEMM: C = act(A1)@W1 [+ A2@W2] + epilogue ----------------
// BM=128, BK=32, 256 threads, 8x(TN) per-thread tile, cols strided by 16.
template <int BN, int TN>
__global__ __launch_bounds__(256, 2)
void gemm_kernel(const float* __restrict__ A1ext, int a1_id, int K1, int reluA1,
                 int a2_id, int K2,
                 const float* __restrict__ W1, const float* __restrict__ W2,
                 const float* __restrict__ b1, const float* __restrict__ b2,
                 float* __restrict__ OutExt, int out_id,
                 int M, int N, int mode)   // mode 0: relu(.+b)*inv; mode 1: .+b1(+b2)
{
    constexpr int BM = 128, BK = 32, TM = 8;
    __shared__ float As[BM][BK];
    __shared__ float Ws[BK][BN];

    const float* A1 = (a1_id < 0) ? A1ext : dbuf(a1_id);
    const float* A2 = dbuf(a2_id);
    float* Out = (out_id < 0) ? OutExt : dbuf(out_id);

    const int tid = threadIdx.x;
    const int tx = tid & 15;        // 16 column groups
    const int ty = tid >> 4;        // 16 row groups
    const int bm = blockIdx.x * BM;
    const int bn = blockIdx.y * BN;

    unsigned long long acc[TM][TN / 2];
#pragma unroll
    for (int r = 0; r < TM; r++)
#pragma unroll
        for (int p = 0; p < TN / 2; p++) acc[r][p] = 0ull;

    for (int pass = 0; pass < 2; ++pass) {
        const float* A = pass ? A2 : A1;
        const float* W = pass ? W2 : W1;
        const int K = pass ? K2 : K1;
        const int doRelu = pass ? 0 : reluA1;
        if (K == 0) continue;
        for (int k0 = 0; k0 < K; k0 += BK) {
            // A tile: 128 x 32 floats = 1024 float4, 4 per thread (coalesced)
#pragma unroll
            for (int it = 0; it < 4; ++it) {
                int i = tid + it * 256;
                int r = i >> 3, c4 = i & 7;
                int row = bm + r;
                float4 v = make_float4(0.f, 0.f, 0.f, 0.f);
                if (row < M)
                    v = reinterpret_cast<const float4*>(A + (size_t)row * K + k0)[c4];
                if (doRelu) {
                    v.x = fmaxf(v.x, 0.f); v.y = fmaxf(v.y, 0.f);
                    v.z = fmaxf(v.z, 0.f); v.w = fmaxf(v.w, 0.f);
                }
                *reinterpret_cast<float4*>(&As[r][c4 * 4]) = v;
            }
            // W tile: 32 x BN floats
            constexpr int WV = (BK * BN / 4) / 256;
#pragma unroll
            for (int it = 0; it < WV; ++it) {
                int i = tid + it * 256;
                int r = i / (BN / 4), c4 = i % (BN / 4);
                float4 v = reinterpret_cast<const float4*>(
                               W + (size_t)(k0 + r) * N + bn)[c4];
                *reinterpret_cast<float4*>(&Ws[r][c4 * 4]) = v;
            }
            __syncthreads();
#pragma unroll 4
            for (int k = 0; k < BK; k++) {
                float a[TM];
#pragma unroll
                for (int r = 0; r < TM; r++) a[r] = As[ty * TM + r][k];
                unsigned long long wp[TN / 2];
#pragma unroll
                for (int p = 0; p < TN / 2; p++) {
                    float w0 = Ws[k][tx + 16 * (2 * p)];
                    float w1 = Ws[k][tx + 16 * (2 * p + 1)];
                    wp[p] = pack2(w0, w1);
                }
#pragma unroll
                for (int r = 0; r < TM; r++) {
                    unsigned long long ar = pack2(a[r], a[r]);
#pragma unroll
                    for (int p = 0; p < TN / 2; p++) ffma2(acc[r][p], ar, wp[p]);
                }
            }
            __syncthreads();
        }
    }

    // epilogue
#pragma unroll
    for (int r = 0; r < TM; r++) {
        int m = bm + ty * TM + r;
        if (m >= M) continue;
        float invm = (mode == 0) ? g_inv[m] : 0.f;
#pragma unroll
        for (int p = 0; p < TN / 2; p++) {
            float2 v = unpack2(acc[r][p]);
            int n0 = bn + tx + 16 * (2 * p);
            int n1 = n0 + 16;
            if (mode == 0) {
                float t0 = fmaxf(v.x + b1[n0], 0.f) * invm;
                float t1 = fmaxf(v.y + b1[n1], 0.f) * invm;
                Out[(size_t)m * N + n0] = t0;
                Out[(size_t)m * N + n1] = t1;
            } else {
                float a0 = b1[n0] + (b2 ? b2[n0] : 0.f);
                float a1 = b1[n1] + (b2 ? b2[n1] : 0.f);
                Out[(size_t)m * N + n0] = v.x + a0;
                Out[(size_t)m * N + n1] = v.y + a1;
            }
        }
    }
}

// ---------------- aggregation: O[t] = (1+eps)*T[t] + sum_{s in adj(t)} T[s] -
// warp-per-node gather; neighbor loop unrolled x4 to raise per-warp MLP
__global__ void aggregate_kernel(int t_id, int o_id) {
    int w = (blockIdx.x * blockDim.x + threadIdx.x) >> 5;
    int lane = threadIdx.x & 31;
    if (w >= NN) return;
    const float4* Tv = reinterpret_cast<const float4*>(dbuf(t_id));
    float4* Ov = reinterpret_cast<float4*>(dbuf(o_id));
    float4 a = Tv[(size_t)w * 32 + lane];
    a.x *= ONE_PE; a.y *= ONE_PE; a.z *= ONE_PE; a.w *= ONE_PE;
    int beg = g_rowptr[w], end = g_rowptr[w + 1];
    int j = beg;
    for (; j + 4 <= end; j += 4) {
        int s0 = g_perm[j + 0];
        int s1 = g_perm[j + 1];
        int s2 = g_perm[j + 2];
        int s3 = g_perm[j + 3];
        float4 v0 = Tv[(size_t)s0 * 32 + lane];
        float4 v1 = Tv[(size_t)s1 * 32 + lane];
        float4 v2 = Tv[(size_t)s2 * 32 + lane];
        float4 v3 = Tv[(size_t)s3 * 32 + lane];
        a.x += v0.x; a.y += v0.y; a.z += v0.z; a.w += v0.w;
        a.x += v1.x; a.y += v1.y; a.z += v1.z; a.w += v1.w;
        a.x += v2.x; a.y += v2.y; a.z += v2.z; a.w += v2.w;
        a.x += v3.x; a.y += v3.y; a.z += v3.z; a.w += v3.w;
    }
    for (; j < end; j++) {
        int s = g_perm[j];
        float4 v = Tv[(size_t)s * 32 + lane];
        a.x += v.x; a.y += v.y; a.z += v.z; a.w += v.w;
    }
    Ov[(size_t)w * 32 + lane] = a;
}

// ---------------- launch ----------------------------------------------------
extern "C" void kernel_launch(void* const* d_in, const int* in_sizes, int n_in,
                              void* d_out, int out_size) {
    const float* x = (const float*)d_in[0];
    const void* ei = d_in[1];
    const int E = in_sizes[1] / 2;
    const float* mpW0 = (const float*)d_in[2];
    const float* mpb0 = (const float*)d_in[3];
    const float* mpW1 = (const float*)d_in[4];
    const float* mpb1 = (const float*)d_in[5];
    const float* mpW2 = (const float*)d_in[6];
    const float* mpb2 = (const float*)d_in[7];
    const float* fcW0 = (const float*)d_in[8];
    const float* fcb0 = (const float*)d_in[9];
    const float* fcW1 = (const float*)d_in[10];
    const float* fcb1 = (const float*)d_in[11];
    const float* pW0  = (const float*)d_in[12];
    const float* pb0  = (const float*)d_in[13];
    const float* pW1  = (const float*)d_in[14];
    const float* pb1  = (const float*)d_in[15];
    const float* outW = (const float*)d_in[16];
    const float* outb = (const float*)d_in[17];
    float* out = (float*)d_out;
    const int M = in_sizes[0] / 128;   // 100000

    // graph preprocessing (CSR by target + source-degree norm)
    detect_kernel<<<1, 1>>>(ei);
    zero_kernel<<<(NN + 255) / 256, 256>>>();
    hist_kernel<<<(E + 255) / 256, 256>>>(ei, E);
    scan_kernel<<<1, 1024>>>(E);
    fill_kernel<<<(E + 255) / 256, 256>>>(ei, E);

    dim3 g128((M + 127) / 128, 1);
    dim3 g512((M + 127) / 128, 4);
    dim3 g64((M + 127) / 128, 1);
    int aggBlocks = (M * 32 + 255) / 256;

    // MP layer 1: x -> bufA (scaled h), aggregate -> bufB
    gemm_kernel<128, 8><<<g128, 256>>>(x, -1, 128, 0, -1, 0,
                                       mpW0, nullptr, mpb0, nullptr,
                                       nullptr, 0, M, 128, 0);
    aggregate_kernel<<<aggBlocks, 256>>>(0, 1);
    // MP layer 2: bufB -> bufA, aggregate -> bufC
    gemm_kernel<128, 8><<<g128, 256>>>(nullptr, 1, 128, 0, -1, 0,
                                       mpW1, nullptr, mpb1, nullptr,
                                       nullptr, 0, M, 128, 0);
    aggregate_kernel<<<aggBlocks, 256>>>(0, 2);
    // MP layer 3: bufC -> bufA, aggregate -> bufB   (bufB = final h, h >= 0)
    gemm_kernel<128, 8><<<g128, 256>>>(nullptr, 2, 128, 0, -1, 0,
                                       mpW2, nullptr, mpb2, nullptr,
                                       nullptr, 0, M, 128, 0);
    aggregate_kernel<<<aggBlocks, 256>>>(0, 1);

    // z1 = relu(h)@fcW0 + h@pW0 + fcb0 + pb0      (h >= 0 so relu(h) == h)
    gemm_kernel<128, 8><<<g512, 256>>>(nullptr, 1, 128, 0, 1, 128,
                                       fcW0, pW0, fcb0, pb0,
                                       nullptr, 3, M, 512, 1);
    // z2 = relu(z1)@fcW1 + h@pW1 + fcb1 + pb1
    gemm_kernel<128, 8><<<g512, 256>>>(nullptr, 3, 512, 1, 1, 128,
                                       fcW1, pW1, fcb1, pb1,
                                       nullptr, 4, M, 512, 1);
    // out = z2@outW + outb
    gemm_kernel<64, 4><<<g64, 256>>>(nullptr, 4, 512, 0, -1, 0,
                                     outW, nullptr, outb, nullptr,
                                     out, -1, M, 64, 1);
}